// round 16
// baseline (speedup 1.0000x reference)
#include <cuda_runtime.h>
#include <cstdint>

// ---------------------------------------------------------------------------
// kernel(i,j) = | prod_k cos((x_ik - y_jk)/2) |
//   = | Px_i * Py_j * prod_k (1 + tx_ik * ty_jk) |,  t = tan(v/2), P = prod cos(v/2)
// prep (PDL primary): float2-vectorized MUFU tan/cos tables, 2 elems/thread.
// qk_kernel (PDL dependent): griddepcontrol.wait, then the proven
//   conflict-free 64x128 f32x2 mainloop (R7/R14 body).
// ---------------------------------------------------------------------------

#define D 16
#define TM 64
#define TN 128
#define THREADS 256   // 16x16; each thread: 4 rows x (4+4) cols

__device__ float g_tx[4096 * D];
__device__ float g_ty[4096 * D];
__device__ float g_px[4096];
__device__ float g_py[4096];

typedef unsigned long long u64;

__device__ __forceinline__ u64 pack2(float lo, float hi) {
    u64 r;
    asm("mov.b64 %0, {%1, %2};" : "=l"(r) : "r"(__float_as_uint(lo)), "r"(__float_as_uint(hi)));
    return r;
}
__device__ __forceinline__ void unpack2(u64 v, float& lo, float& hi) {
    unsigned a, b;
    asm("mov.b64 {%0, %1}, %2;" : "=r"(a), "=r"(b) : "l"(v));
    lo = __uint_as_float(a);
    hi = __uint_as_float(b);
}
__device__ __forceinline__ u64 mul2(u64 a, u64 b) {
    u64 r;
    asm("mul.rn.f32x2 %0, %1, %2;" : "=l"(r) : "l"(a), "l"(b));
    return r;
}
__device__ __forceinline__ u64 fma2(u64 a, u64 b, u64 c) {
    u64 r;
    asm("fma.rn.f32x2 %0, %1, %2, %3;" : "=l"(r) : "l"(a), "l"(b), "l"(c));
    return r;
}

__device__ __forceinline__ void tan_cos(float h, float& tn, float& c) {
    c = __cosf(h);
    float s = __sinf(h);
    if (fabsf(c) < 0.01f) {              // rare exact fallback near cos zero
        sincosf(h, &s, &c);
        if (fabsf(c) < 1e-20f) c = copysignf(1e-20f, c);
    }
    tn = __fdividef(s, c);
}

// ---------------------------------------------------------------------------
// PDL primary: both tables, float2-vectorized (2 elements per thread).
// Thread t handles elements {2t, 2t+1}; one row (16 elems) spans 8 lanes, so
// the cos-product needs local pair product + 3 shfl_xor steps (1,2,4).
// ---------------------------------------------------------------------------
__global__ void prep(const float* __restrict__ x, const float* __restrict__ y,
                     int nx, int ny) {
    asm volatile("griddepcontrol.launch_dependents;" ::: "memory");

    int t = blockIdx.x * blockDim.x + threadIdx.x;   // pair index
    int npx = nx >> 1;                               // x pairs
    int total = (nx + ny) >> 1;
    bool live = t < total;
    bool inx = t < npx;
    int u = inx ? t : t - npx;                       // pair index within table
    float2 v = make_float2(0.0f, 0.0f);
    if (live) {
        const float2* src = inx ? (const float2*)x : (const float2*)y;
        v = src[u];
    }
    float t0, c0, t1, c1;
    tan_cos(0.5f * v.x, t0, c0);
    tan_cos(0.5f * v.y, t1, c1);

    float p = c0 * c1;                               // 2 of the 16 factors
    p *= __shfl_xor_sync(0xffffffffu, p, 1);
    p *= __shfl_xor_sync(0xffffffffu, p, 2);
    p *= __shfl_xor_sync(0xffffffffu, p, 4);
    if (live) {
        float2* dst = inx ? (float2*)g_tx : (float2*)g_ty;
        dst[u] = make_float2(t0, t1);
        if ((u & 7) == 0) {                          // first pair of each row
            int row = u >> 3;
            if (inx) g_px[row] = p; else g_py[row] = p;
        }
    }
}

// ---------------------------------------------------------------------------
// PDL dependent: R14 mainloop verbatim, gated by griddepcontrol.wait.
// ---------------------------------------------------------------------------
__global__ __launch_bounds__(THREADS, 4)
void qk_kernel(float* __restrict__ out, int n, int m) {
    __shared__ __align__(16) u64 sxt[D][TM + 2];     // x tans dup (t,t), pitch 66
    __shared__ __align__(16) float syt[D][TN + 4];   // y tans, pitch 132
    __shared__ __align__(16) u64 spx[TM];
    __shared__ __align__(16) float spy[TN];

    const int tid = threadIdx.x;
    const int i0 = blockIdx.y * TM;
    const int j0 = blockIdx.x * TN;

    // Gate: primary grid (prep) fully complete & visible.
    asm volatile("griddepcontrol.wait;" ::: "memory");

    // Kick off the small scalar loads first so they overlap the fill loops.
    if (tid < TM) {
        float p = g_px[i0 + tid];
        spx[tid] = pack2(p, p);
    } else if (tid < TM + TN) {
        spy[tid - TM] = g_py[j0 + tid - TM];
    }

    // ---- fill shared (coalesced global reads) ----
    #pragma unroll
    for (int idx = tid; idx < TM * D; idx += THREADS) {
        int i = idx >> 4;
        int k = idx & (D - 1);
        float vx = g_tx[(i0 + i) * D + k];
        sxt[k][i] = pack2(vx, vx);
    }
    #pragma unroll
    for (int idx = tid; idx < TN * D; idx += THREADS) {
        int j = idx >> 4;
        int k = idx & (D - 1);
        syt[k][j] = g_ty[(j0 + j) * D + k];
    }
    __syncthreads();

    const int tx = tid & 15;
    const int ty = tid >> 4;
    const int ib = ty * 4;        // even -> 16B-aligned LDS.128 on sxt rows
    const int ja = tx * 4;        // 16B lane stride, conflict-free
    const int jB = 64 + tx * 4;

    const u64 one2 = pack2(1.0f, 1.0f);
    u64 acc[4][4];
    #pragma unroll
    for (int r = 0; r < 4; ++r)
        #pragma unroll
        for (int p = 0; p < 4; ++p)
            acc[r][p] = one2;

    #pragma unroll
    for (int k = 0; k < D; ++k) {
        ulonglong2 ya = *reinterpret_cast<const ulonglong2*>(&syt[k][ja]);
        ulonglong2 yb = *reinterpret_cast<const ulonglong2*>(&syt[k][jB]);
        ulonglong2 xa = *reinterpret_cast<const ulonglong2*>(&sxt[k][ib]);
        ulonglong2 xb = *reinterpret_cast<const ulonglong2*>(&sxt[k][ib + 2]);
        u64 xt0 = xa.x, xt1 = xa.y, xt2 = xb.x, xt3 = xb.y;
        acc[0][0] = fma2(acc[0][0], mul2(xt0, ya.x), acc[0][0]);
        acc[0][1] = fma2(acc[0][1], mul2(xt0, ya.y), acc[0][1]);
        acc[0][2] = fma2(acc[0][2], mul2(xt0, yb.x), acc[0][2]);
        acc[0][3] = fma2(acc[0][3], mul2(xt0, yb.y), acc[0][3]);
        acc[1][0] = fma2(acc[1][0], mul2(xt1, ya.x), acc[1][0]);
        acc[1][1] = fma2(acc[1][1], mul2(xt1, ya.y), acc[1][1]);
        acc[1][2] = fma2(acc[1][2], mul2(xt1, yb.x), acc[1][2]);
        acc[1][3] = fma2(acc[1][3], mul2(xt1, yb.y), acc[1][3]);
        acc[2][0] = fma2(acc[2][0], mul2(xt2, ya.x), acc[2][0]);
        acc[2][1] = fma2(acc[2][1], mul2(xt2, ya.y), acc[2][1]);
        acc[2][2] = fma2(acc[2][2], mul2(xt2, yb.x), acc[2][2]);
        acc[2][3] = fma2(acc[2][3], mul2(xt2, yb.y), acc[2][3]);
        acc[3][0] = fma2(acc[3][0], mul2(xt3, ya.x), acc[3][0]);
        acc[3][1] = fma2(acc[3][1], mul2(xt3, ya.y), acc[3][1]);
        acc[3][2] = fma2(acc[3][2], mul2(xt3, yb.x), acc[3][2]);
        acc[3][3] = fma2(acc[3][3], mul2(xt3, yb.y), acc[3][3]);
    }

    // ---- epilogue: scale by Px*Py, abs, two coalesced float4 stores/row ---
    ulonglong2 pya = *reinterpret_cast<const ulonglong2*>(&spy[ja]);
    ulonglong2 pyb = *reinterpret_cast<const ulonglong2*>(&spy[jB]);
    #pragma unroll
    for (int r = 0; r < 4; ++r) {
        u64 px2 = spx[ib + r];
        u64 v0 = mul2(mul2(acc[r][0], px2), pya.x);
        u64 v1 = mul2(mul2(acc[r][1], px2), pya.y);
        u64 v2 = mul2(mul2(acc[r][2], px2), pyb.x);
        u64 v3 = mul2(mul2(acc[r][3], px2), pyb.y);
        float a0, a1, b0, b1, c0, c1, d0, d1;
        unpack2(v0, a0, a1);
        unpack2(v1, b0, b1);
        unpack2(v2, c0, c1);
        unpack2(v3, d0, d1);
        float* row = &out[(size_t)(i0 + ib + r) * m + j0];
        *reinterpret_cast<float4*>(row + ja) =
            make_float4(fabsf(a0), fabsf(a1), fabsf(b0), fabsf(b1));
        *reinterpret_cast<float4*>(row + jB) =
            make_float4(fabsf(c0), fabsf(c1), fabsf(d0), fabsf(d1));
    }
}

// ---------------------------------------------------------------------------
extern "C" void kernel_launch(void* const* d_in, const int* in_sizes, int n_in,
                              void* d_out, int out_size) {
    const float* x = (const float*)d_in[0];
    const float* y = (const float*)d_in[1];
    float* out = (float*)d_out;

    int nx = in_sizes[0];      // n * D
    int ny = in_sizes[1];      // m * D
    int n = nx / D;
    int m = ny / D;

    int pairs = (nx + ny) >> 1;
    prep<<<(pairs + 255) / 256, 256>>>(x, y, nx, ny);

    cudaLaunchConfig_t cfg = {};
    cfg.gridDim = dim3(m / TN, n / TM);
    cfg.blockDim = dim3(THREADS);
    cfg.dynamicSmemBytes = 0;
    cfg.stream = 0;
    cudaLaunchAttribute attr[1];
    attr[0].id = cudaLaunchAttributeProgrammaticStreamSerialization;
    attr[0].val.programmaticStreamSerializationAllowed = 1;
    cfg.attrs = attr;
    cfg.numAttrs = 1;
    cudaLaunchKernelEx(&cfg, qk_kernel, out, n, m);
}